// round 1
// baseline (speedup 1.0000x reference)
#include <cuda_runtime.h>
#include <cuda_bf16.h>
#include <math.h>

// Problem constants
#define BB   2
#define SS   2048
#define DD   1024
#define HH   16
#define DK   64
#define HALF 64

// ---------------- scratch (device globals; no runtime allocation) ----------
__device__ float g_q[BB*HH*SS*DK];   // [B,H,S,DK]
__device__ float g_k[BB*HH*SS*DK];
__device__ float g_v[BB*HH*SS*DK];
__device__ float g_x[BB*SS*DD];      // [B,S,D] attention output (pre out-proj)

// ---------------- SGEMM: 128x128 tile, 8x8 per thread, BK=16 ---------------
__device__ __forceinline__ void gemm_tile(const float* __restrict__ A,
                                          const float* __restrict__ W,
                                          const float* __restrict__ bias,
                                          float* __restrict__ C,
                                          bool permuted)
{
    __shared__ float As[16][132];
    __shared__ float Bs[16][128];

    const int tid = threadIdx.x;
    const int tx  = tid & 15;        // 0..15  -> n
    const int ty  = tid >> 4;        // 0..15  -> m
    const int m0  = blockIdx.y * 128;
    const int n0  = blockIdx.x * 128;

    float acc[8][8];
    #pragma unroll
    for (int i = 0; i < 8; i++)
        #pragma unroll
        for (int j = 0; j < 8; j++) acc[i][j] = 0.f;

    for (int k0 = 0; k0 < DD; k0 += 16) {
        // A tile: 128 rows x 16 cols (store transposed into As[k][m])
        #pragma unroll
        for (int i = 0; i < 2; i++) {
            int f = tid + i * 256;          // 512 float4
            int r = f >> 2, c = (f & 3) << 2;
            float4 av = *reinterpret_cast<const float4*>(&A[(size_t)(m0 + r) * DD + k0 + c]);
            As[c + 0][r] = av.x; As[c + 1][r] = av.y;
            As[c + 2][r] = av.z; As[c + 3][r] = av.w;
        }
        // B tile: 16 rows x 128 cols
        #pragma unroll
        for (int i = 0; i < 2; i++) {
            int f = tid + i * 256;          // 512 float4
            int r = f >> 5, c = (f & 31) << 2;
            *reinterpret_cast<float4*>(&Bs[r][c]) =
                *reinterpret_cast<const float4*>(&W[(size_t)(k0 + r) * DD + n0 + c]);
        }
        __syncthreads();

        #pragma unroll
        for (int kk = 0; kk < 16; ++kk) {
            float af[8], bf[8];
            #pragma unroll
            for (int i = 0; i < 8; i++) af[i] = As[kk][ty * 8 + i];
            #pragma unroll
            for (int j = 0; j < 8; j++) bf[j] = Bs[kk][tx * 8 + j];
            #pragma unroll
            for (int i = 0; i < 8; i++)
                #pragma unroll
                for (int j = 0; j < 8; j++) acc[i][j] += af[i] * bf[j];
        }
        __syncthreads();
    }

    // epilogue: + bias, store (permuted -> [B,H,S,DK], else row-major [M,N])
    #pragma unroll
    for (int i = 0; i < 8; i++) {
        int m = m0 + ty * 8 + i;
        int b = m >> 11;            // /2048
        int s = m & 2047;
        #pragma unroll
        for (int j = 0; j < 8; j++) {
            int n = n0 + tx * 8 + j;
            float v = acc[i][j] + bias[n];
            if (permuted) {
                int h = n >> 6, dk = n & 63;
                C[((size_t)(b * HH + h) * SS + s) * DK + dk] = v;
            } else {
                C[(size_t)m * DD + n] = v;
            }
        }
    }
}

__global__ __launch_bounds__(256, 2) void qkv_proj_kernel(
    const float* __restrict__ q, const float* __restrict__ k, const float* __restrict__ v,
    const float* __restrict__ Wq, const float* __restrict__ Wk, const float* __restrict__ Wv,
    const float* __restrict__ bq, const float* __restrict__ bk, const float* __restrict__ bv)
{
    int w = blockIdx.z;
    const float* A  = (w == 0) ? q  : (w == 1) ? k  : v;
    const float* W  = (w == 0) ? Wq : (w == 1) ? Wk : Wv;
    const float* bi = (w == 0) ? bq : (w == 1) ? bk : bv;
    float* C        = (w == 0) ? g_q : (w == 1) ? g_k : g_v;
    gemm_tile(A, W, bi, C, true);
}

__global__ __launch_bounds__(256, 2) void out_proj_kernel(
    const float* __restrict__ Wo, const float* __restrict__ bo, float* __restrict__ out)
{
    gemm_tile(g_x, Wo, bo, out, false);
}

// ---------------- banded attention ------------------------------------------
// One block per (bh, 64-query tile). Keys needed: [i0-64, i0+127+? ) -> 192 rows.
// smem: Qs 64x65, Ks 192x65, Vs 192x68, Ps 64x132  = 152,576 B (dynamic)
#define Q_STRIDE 65
#define K_STRIDE 65
#define V_STRIDE 68
#define P_STRIDE 132
#define SMEM_ATTN ((64*Q_STRIDE + 192*K_STRIDE + 192*V_STRIDE + 64*P_STRIDE) * 4)

__global__ __launch_bounds__(256) void attn_kernel(float* __restrict__ attn_out)
{
    extern __shared__ float sm[];
    float* Qs = sm;
    float* Ks = Qs + 64 * Q_STRIDE;
    float* Vs = Ks + 192 * K_STRIDE;
    float* Ps = Vs + 192 * V_STRIDE;

    const int tid = threadIdx.x;
    const int bh  = blockIdx.y;
    const int i0  = blockIdx.x * 64;
    const int b   = bh >> 4, h = bh & 15;

    const float* Qg = g_q + (size_t)bh * SS * DK;
    const float* Kg = g_k + (size_t)bh * SS * DK;
    const float* Vg = g_v + (size_t)bh * SS * DK;

    // ---- load Q (64x64) ----
    #pragma unroll
    for (int i = 0; i < 4; i++) {
        int f = tid + i * 256;            // 1024 float4
        int r = f >> 4, c = (f & 15) << 2;
        float4 v = *reinterpret_cast<const float4*>(&Qg[(size_t)(i0 + r) * DK + c]);
        float* d = &Qs[r * Q_STRIDE + c];
        d[0] = v.x; d[1] = v.y; d[2] = v.z; d[3] = v.w;
    }
    // ---- load K,V (192x64), zero-fill out of range ----
    const int kg0 = i0 - HALF;
    #pragma unroll
    for (int i = 0; i < 12; i++) {
        int f = tid + i * 256;            // 3072 float4
        int r = f >> 4, c = (f & 15) << 2;
        int gr = kg0 + r;
        float4 kv = make_float4(0.f, 0.f, 0.f, 0.f);
        float4 vv = kv;
        if (gr >= 0 && gr < SS) {
            kv = *reinterpret_cast<const float4*>(&Kg[(size_t)gr * DK + c]);
            vv = *reinterpret_cast<const float4*>(&Vg[(size_t)gr * DK + c]);
        }
        float* kd = &Ks[r * K_STRIDE + c];
        kd[0] = kv.x; kd[1] = kv.y; kd[2] = kv.z; kd[3] = kv.w;
        *reinterpret_cast<float4*>(&Vs[r * V_STRIDE + c]) = vv;
    }
    __syncthreads();

    // ---- scores + softmax: warp handles 8 query rows, lanes split the 129 keys
    const int warp = tid >> 5, lane = tid & 31;
    for (int r8 = 0; r8 < 8; ++r8) {
        const int il = warp * 8 + r8;     // local query row
        const int qg = i0 + il;
        float acc[5];
        const float* kr[5];
        bool  val[5];
        #pragma unroll
        for (int g = 0; g < 5; ++g) {
            int t = lane + 32 * g;        // position within 129-window
            int j = qg - HALF + t;
            val[g] = (t <= 128) && (j >= 0) && (j < SS);
            kr[g]  = &Ks[(val[g] ? (il + t) : 0) * K_STRIDE];
            acc[g] = 0.f;
        }
        const float* qr = &Qs[il * Q_STRIDE];
        #pragma unroll 8
        for (int d = 0; d < DK; ++d) {
            float qv = qr[d];
            #pragma unroll
            for (int g = 0; g < 5; ++g) acc[g] += qv * kr[g][d];
        }
        float mx = -INFINITY;
        #pragma unroll
        for (int g = 0; g < 5; ++g) {
            acc[g] = val[g] ? acc[g] * 0.125f : -INFINITY;   // 1/sqrt(64)
            mx = fmaxf(mx, acc[g]);
        }
        #pragma unroll
        for (int o = 16; o > 0; o >>= 1) mx = fmaxf(mx, __shfl_xor_sync(0xffffffffu, mx, o));
        float sum = 0.f;
        #pragma unroll
        for (int g = 0; g < 5; ++g) {
            float e = __expf(acc[g] - mx);                   // -inf -> 0
            acc[g] = e; sum += e;
        }
        #pragma unroll
        for (int o = 16; o > 0; o >>= 1) sum += __shfl_xor_sync(0xffffffffu, sum, o);
        float inv = 1.0f / sum;
        #pragma unroll
        for (int g = 0; g < 5; ++g) {
            int t = lane + 32 * g;
            if (t <= 128) Ps[il * P_STRIDE + t] = acc[g] * inv;
        }
    }
    __syncthreads();

    // ---- P @ V : thread owns (row, 16 dk) ----
    {
        const int il  = tid >> 2;
        const int dk0 = (tid & 3) << 4;
        const int qg  = i0 + il;
        int t0 = (qg >= HALF) ? 0 : (HALF - qg);
        int t1 = 128;
        int tmax = (SS - 1 - qg) + HALF;
        if (tmax < t1) t1 = tmax;

        float acc[16];
        #pragma unroll
        for (int e = 0; e < 16; e++) acc[e] = 0.f;
        for (int t = t0; t <= t1; ++t) {
            float p = Ps[il * P_STRIDE + t];
            const float* vr = &Vs[(il + t) * V_STRIDE + dk0];
            #pragma unroll
            for (int e4 = 0; e4 < 4; e4++) {
                float4 v = *reinterpret_cast<const float4*>(&vr[e4 * 4]);
                acc[e4*4+0] += p * v.x; acc[e4*4+1] += p * v.y;
                acc[e4*4+2] += p * v.z; acc[e4*4+3] += p * v.w;
            }
        }
        float* xo = &g_x[((size_t)b * SS + qg) * DD + h * DK + dk0];
        #pragma unroll
        for (int e4 = 0; e4 < 4; e4++)
            *reinterpret_cast<float4*>(&xo[e4 * 4]) =
                make_float4(acc[e4*4], acc[e4*4+1], acc[e4*4+2], acc[e4*4+3]);
    }

    // ---- write band of attn matrix (rest was memset to 0) ----
    for (int idx = tid; idx < 64 * 129; idx += 256) {
        int r = idx / 129;
        int t = idx - r * 129;
        int qg = i0 + r;
        int j  = qg - HALF + t;
        if (j >= 0 && j < SS)
            attn_out[((size_t)bh * SS + qg) * SS + j] = Ps[r * P_STRIDE + t];
    }
}

// ---------------- launch -----------------------------------------------------
extern "C" void kernel_launch(void* const* d_in, const int* in_sizes, int n_in,
                              void* d_out, int out_size)
{
    const float* query = (const float*)d_in[0];
    const float* key   = (const float*)d_in[1];
    const float* value = (const float*)d_in[2];
    const float* Wq    = (const float*)d_in[3];
    const float* bq    = (const float*)d_in[4];
    const float* Wk    = (const float*)d_in[5];
    const float* bk    = (const float*)d_in[6];
    const float* Wv    = (const float*)d_in[7];
    const float* bv    = (const float*)d_in[8];
    const float* Wo    = (const float*)d_in[9];
    const float* bo    = (const float*)d_in[10];

    float* out  = (float*)d_out;
    float* attn = out + (size_t)BB * SS * DD;

    // Q/K/V projections (fused into one launch via blockIdx.z)
    qkv_proj_kernel<<<dim3(8, 32, 3), 256>>>(query, key, value, Wq, Wk, Wv, bq, bk, bv);

    // zero attn matrix (out-of-band entries are exactly 0 in the reference)
    cudaMemsetAsync(attn, 0, (size_t)BB * HH * SS * SS * sizeof(float));

    // banded attention
    cudaFuncSetAttribute(attn_kernel, cudaFuncAttributeMaxDynamicSharedMemorySize, SMEM_ATTN);
    attn_kernel<<<dim3(SS / 64, BB * HH), 256, SMEM_ATTN>>>(attn);

    // output projection
    out_proj_kernel<<<dim3(8, 32), 256>>>(Wo, bo, out);
}

// round 2
// speedup vs baseline: 2.1447x; 2.1447x over previous
#include <cuda_runtime.h>
#include <cuda_bf16.h>
#include <math.h>

// Problem constants
#define BB   2
#define SS   2048
#define DD   1024
#define HH   16
#define DK   64
#define HALF 64

// ---------------- scratch (device globals; no runtime allocation) ----------
__device__ float g_q[BB*HH*SS*DK];   // [B,H,S,DK]
__device__ float g_k[BB*HH*SS*DK];
__device__ float g_v[BB*HH*SS*DK];
__device__ float g_x[BB*SS*DD];      // [B,S,D] attention output (pre out-proj)

// ---------------- helpers ----------------------------------------------------
__device__ __forceinline__ unsigned cvta_sh(const void* p) {
    return (unsigned)__cvta_generic_to_shared(p);
}
__device__ __forceinline__ unsigned cvt_tf32(float x) {
    unsigned r; asm("cvt.rna.tf32.f32 %0, %1;" : "=r"(r) : "f"(x)); return r;
}
#define CP_ASYNC16(saddr, gaddr) \
    asm volatile("cp.async.cg.shared.global [%0], [%1], 16;\n" :: "r"(saddr), "l"(gaddr))
#define CP_COMMIT() asm volatile("cp.async.commit_group;\n" ::)
#define CP_WAIT(N)  asm volatile("cp.async.wait_group %0;\n" :: "n"(N))

// ---------------- TF32 tensor-core GEMM --------------------------------------
// C[M,N] = A[M,K=1024] @ W[K,N=1024] + bias ; 128x128 block, BK=32,
// 8 warps of 64x32, m16n8k8 tf32 mma. cp.async double-buffered.
#define AS_STRIDE 36     // 128 x 36 floats per stage (conflict-free frag loads)
#define BS_STRIDE 136    // 32 x 136 floats per stage
#define AS_STAGE  (128 * AS_STRIDE)
#define BS_STAGE  (32 * BS_STRIDE)
#define SMEM_GEMM ((2 * (AS_STAGE + BS_STAGE)) * 4)   // 71680 B

__device__ __forceinline__ void gemm_load_stage(
    const float* __restrict__ A, const float* __restrict__ W,
    float* As, float* Bs, int stage, int k0, int m0, int n0, int tid)
{
    float* Ad = As + stage * AS_STAGE;
    float* Bd = Bs + stage * BS_STAGE;
    #pragma unroll
    for (int i = 0; i < 4; i++) {
        int f = tid + i * 256;          // 1024 float4 for A: 128 rows x 8 f4
        int r = f >> 3, c4 = f & 7;
        CP_ASYNC16(cvta_sh(&Ad[r * AS_STRIDE + c4 * 4]),
                   &A[(size_t)(m0 + r) * DD + k0 + c4 * 4]);
    }
    #pragma unroll
    for (int i = 0; i < 4; i++) {
        int f = tid + i * 256;          // 1024 float4 for B: 32 rows x 32 f4
        int r = f >> 5, c4 = f & 31;
        CP_ASYNC16(cvta_sh(&Bd[r * BS_STRIDE + c4 * 4]),
                   &W[(size_t)(k0 + r) * DD + n0 + c4 * 4]);
    }
    CP_COMMIT();
}

__device__ __forceinline__ void gemm_tf32(const float* __restrict__ A,
                                          const float* __restrict__ W,
                                          const float* __restrict__ bias,
                                          float* __restrict__ C,
                                          bool permuted)
{
    extern __shared__ float sm[];
    float* As = sm;
    float* Bs = sm + 2 * AS_STAGE;

    const int tid  = threadIdx.x;
    const int lane = tid & 31;
    const int wid  = tid >> 5;
    const int wm   = wid >> 2;           // 0..1
    const int wn   = wid & 3;            // 0..3
    const int m0   = blockIdx.y * 128;
    const int n0   = blockIdx.x * 128;
    const int g    = lane >> 2;          // 0..7
    const int kq   = lane & 3;           // 0..3

    float acc[4][4][4];
    #pragma unroll
    for (int i = 0; i < 4; i++)
        #pragma unroll
        for (int j = 0; j < 4; j++)
            #pragma unroll
            for (int e = 0; e < 4; e++) acc[i][j][e] = 0.f;

    gemm_load_stage(A, W, As, Bs, 0, 0, m0, n0, tid);

    #pragma unroll 1
    for (int t = 0; t < DD / 32; ++t) {
        if (t + 1 < DD / 32) {
            gemm_load_stage(A, W, As, Bs, (t + 1) & 1, (t + 1) * 32, m0, n0, tid);
            CP_WAIT(1);
        } else {
            CP_WAIT(0);
        }
        __syncthreads();

        const float* Ab = As + (t & 1) * AS_STAGE;
        const float* Bb = Bs + (t & 1) * BS_STAGE;

        #pragma unroll
        for (int kk = 0; kk < 4; ++kk) {
            const int kr = kk * 8 + kq;
            unsigned a[4][4], b[4][2];
            #pragma unroll
            for (int mf = 0; mf < 4; ++mf) {
                int m = wm * 64 + mf * 16 + g;
                a[mf][0] = cvt_tf32(Ab[m * AS_STRIDE + kr]);
                a[mf][1] = cvt_tf32(Ab[(m + 8) * AS_STRIDE + kr]);
                a[mf][2] = cvt_tf32(Ab[m * AS_STRIDE + kr + 4]);
                a[mf][3] = cvt_tf32(Ab[(m + 8) * AS_STRIDE + kr + 4]);
            }
            #pragma unroll
            for (int nf = 0; nf < 4; ++nf) {
                int n = wn * 32 + nf * 8 + g;
                b[nf][0] = cvt_tf32(Bb[kr * BS_STRIDE + n]);
                b[nf][1] = cvt_tf32(Bb[(kr + 4) * BS_STRIDE + n]);
            }
            #pragma unroll
            for (int mf = 0; mf < 4; ++mf)
                #pragma unroll
                for (int nf = 0; nf < 4; ++nf) {
                    asm volatile(
                        "mma.sync.aligned.m16n8k8.row.col.f32.tf32.tf32.f32 "
                        "{%0,%1,%2,%3}, {%4,%5,%6,%7}, {%8,%9}, {%0,%1,%2,%3};"
                        : "+f"(acc[mf][nf][0]), "+f"(acc[mf][nf][1]),
                          "+f"(acc[mf][nf][2]), "+f"(acc[mf][nf][3])
                        : "r"(a[mf][0]), "r"(a[mf][1]), "r"(a[mf][2]), "r"(a[mf][3]),
                          "r"(b[nf][0]), "r"(b[nf][1]));
                }
        }
        __syncthreads();
    }

    // epilogue
    #pragma unroll
    for (int mf = 0; mf < 4; ++mf) {
        #pragma unroll
        for (int nf = 0; nf < 4; ++nf) {
            int m = m0 + wm * 64 + mf * 16 + g;
            int n = n0 + wn * 32 + nf * 8 + 2 * kq;
            float bn0 = bias[n], bn1 = bias[n + 1];
            #pragma unroll
            for (int half = 0; half < 2; ++half) {
                int mm = m + half * 8;
                float v0 = acc[mf][nf][half * 2 + 0] + bn0;
                float v1 = acc[mf][nf][half * 2 + 1] + bn1;
                int bb = mm >> 11, s = mm & 2047;
                if (permuted) {
                    int h = n >> 6, dk = n & 63;
                    float2* dst = reinterpret_cast<float2*>(
                        &C[((size_t)(bb * HH + h) * SS + s) * DK + dk]);
                    *dst = make_float2(v0, v1);
                } else {
                    float2* dst = reinterpret_cast<float2*>(&C[(size_t)mm * DD + n]);
                    *dst = make_float2(v0, v1);
                }
            }
        }
    }
}

__global__ __launch_bounds__(256, 2) void qkv_proj_kernel(
    const float* __restrict__ q, const float* __restrict__ k, const float* __restrict__ v,
    const float* __restrict__ Wq, const float* __restrict__ Wk, const float* __restrict__ Wv,
    const float* __restrict__ bq, const float* __restrict__ bk, const float* __restrict__ bv)
{
    int w = blockIdx.z;
    const float* A  = (w == 0) ? q  : (w == 1) ? k  : v;
    const float* W  = (w == 0) ? Wq : (w == 1) ? Wk : Wv;
    const float* bi = (w == 0) ? bq : (w == 1) ? bk : bv;
    float* C        = (w == 0) ? g_q : (w == 1) ? g_k : g_v;
    gemm_tf32(A, W, bi, C, true);
}

__global__ __launch_bounds__(256, 2) void out_proj_kernel(
    const float* __restrict__ Wo, const float* __restrict__ bo, float* __restrict__ out)
{
    gemm_tf32(g_x, Wo, bo, out, false);
}

// ---------------- banded attention ------------------------------------------
#define Q_STRIDE 65
#define K_STRIDE 65
#define V_STRIDE 68
#define P_STRIDE 132
#define SMEM_ATTN ((64*Q_STRIDE + 192*K_STRIDE + 192*V_STRIDE + 64*P_STRIDE) * 4)

__global__ __launch_bounds__(256) void attn_kernel(float* __restrict__ attn_out)
{
    extern __shared__ float sm[];
    float* Qs = sm;
    float* Ks = Qs + 64 * Q_STRIDE;
    float* Vs = Ks + 192 * K_STRIDE;
    float* Ps = Vs + 192 * V_STRIDE;

    const int tid = threadIdx.x;
    const int bh  = blockIdx.y;
    const int i0  = blockIdx.x * 64;
    const int b   = bh >> 4, h = bh & 15;

    const float* Qg = g_q + (size_t)bh * SS * DK;
    const float* Kg = g_k + (size_t)bh * SS * DK;
    const float* Vg = g_v + (size_t)bh * SS * DK;

    // ---- load Q (64x64) ----
    #pragma unroll
    for (int i = 0; i < 4; i++) {
        int f = tid + i * 256;
        int r = f >> 4, c = (f & 15) << 2;
        float4 v = *reinterpret_cast<const float4*>(&Qg[(size_t)(i0 + r) * DK + c]);
        float* d = &Qs[r * Q_STRIDE + c];
        d[0] = v.x; d[1] = v.y; d[2] = v.z; d[3] = v.w;
    }
    // ---- load K,V (192x64), zero-fill out of range ----
    const int kg0 = i0 - HALF;
    #pragma unroll
    for (int i = 0; i < 12; i++) {
        int f = tid + i * 256;
        int r = f >> 4, c = (f & 15) << 2;
        int gr = kg0 + r;
        float4 kv = make_float4(0.f, 0.f, 0.f, 0.f);
        float4 vv = kv;
        if (gr >= 0 && gr < SS) {
            kv = *reinterpret_cast<const float4*>(&Kg[(size_t)gr * DK + c]);
            vv = *reinterpret_cast<const float4*>(&Vg[(size_t)gr * DK + c]);
        }
        float* kd = &Ks[r * K_STRIDE + c];
        kd[0] = kv.x; kd[1] = kv.y; kd[2] = kv.z; kd[3] = kv.w;
        *reinterpret_cast<float4*>(&Vs[r * V_STRIDE + c]) = vv;
    }
    __syncthreads();

    // ---- scores + softmax ----
    const int warp = tid >> 5, lane = tid & 31;
    for (int r8 = 0; r8 < 8; ++r8) {
        const int il = warp * 8 + r8;
        const int qg = i0 + il;
        float acc[5];
        const float* kr[5];
        bool  val[5];
        #pragma unroll
        for (int gg = 0; gg < 5; ++gg) {
            int t = lane + 32 * gg;
            int j = qg - HALF + t;
            val[gg] = (t <= 128) && (j >= 0) && (j < SS);
            kr[gg]  = &Ks[(val[gg] ? (il + t) : 0) * K_STRIDE];
            acc[gg] = 0.f;
        }
        const float* qr = &Qs[il * Q_STRIDE];
        #pragma unroll 8
        for (int d = 0; d < DK; ++d) {
            float qv = qr[d];
            #pragma unroll
            for (int gg = 0; gg < 5; ++gg) acc[gg] += qv * kr[gg][d];
        }
        float mx = -INFINITY;
        #pragma unroll
        for (int gg = 0; gg < 5; ++gg) {
            acc[gg] = val[gg] ? acc[gg] * 0.125f : -INFINITY;
            mx = fmaxf(mx, acc[gg]);
        }
        #pragma unroll
        for (int o = 16; o > 0; o >>= 1) mx = fmaxf(mx, __shfl_xor_sync(0xffffffffu, mx, o));
        float sum = 0.f;
        #pragma unroll
        for (int gg = 0; gg < 5; ++gg) {
            float e = __expf(acc[gg] - mx);
            acc[gg] = e; sum += e;
        }
        #pragma unroll
        for (int o = 16; o > 0; o >>= 1) sum += __shfl_xor_sync(0xffffffffu, sum, o);
        float inv = 1.0f / sum;
        #pragma unroll
        for (int gg = 0; gg < 5; ++gg) {
            int t = lane + 32 * gg;
            if (t <= 128) Ps[il * P_STRIDE + t] = acc[gg] * inv;
        }
    }
    __syncthreads();

    // ---- P @ V ----
    {
        const int il  = tid >> 2;
        const int dk0 = (tid & 3) << 4;
        const int qg  = i0 + il;
        int t0 = (qg >= HALF) ? 0 : (HALF - qg);
        int t1 = 128;
        int tmax = (SS - 1 - qg) + HALF;
        if (tmax < t1) t1 = tmax;

        float acc[16];
        #pragma unroll
        for (int e = 0; e < 16; e++) acc[e] = 0.f;
        for (int t = t0; t <= t1; ++t) {
            float p = Ps[il * P_STRIDE + t];
            const float* vr = &Vs[(il + t) * V_STRIDE + dk0];
            #pragma unroll
            for (int e4 = 0; e4 < 4; e4++) {
                float4 v = *reinterpret_cast<const float4*>(&vr[e4 * 4]);
                acc[e4*4+0] += p * v.x; acc[e4*4+1] += p * v.y;
                acc[e4*4+2] += p * v.z; acc[e4*4+3] += p * v.w;
            }
        }
        float* xo = &g_x[((size_t)b * SS + qg) * DD + h * DK + dk0];
        #pragma unroll
        for (int e4 = 0; e4 < 4; e4++)
            *reinterpret_cast<float4*>(&xo[e4 * 4]) =
                make_float4(acc[e4*4], acc[e4*4+1], acc[e4*4+2], acc[e4*4+3]);
    }

    // ---- write FULL rows of attn matrix (band + zeros; replaces memset) ----
    {
        float* base = attn_out + (size_t)bh * SS * SS;
        for (int idx = tid; idx < 64 * (SS / 4); idx += 256) {
            int r  = idx >> 9;             // /512
            int c4 = idx & 511;
            int j0 = c4 << 2;
            int qg = i0 + r;
            int tb = j0 - (qg - HALF);     // window offset of first element
            float4 o;
            float* po = reinterpret_cast<float*>(&o);
            #pragma unroll
            for (int e = 0; e < 4; e++) {
                int t = tb + e;
                po[e] = (t >= 0 && t <= 128) ? Ps[r * P_STRIDE + t] : 0.f;
            }
            *reinterpret_cast<float4*>(&base[(size_t)qg * SS + j0]) = o;
        }
    }
}

// ---------------- launch -----------------------------------------------------
extern "C" void kernel_launch(void* const* d_in, const int* in_sizes, int n_in,
                              void* d_out, int out_size)
{
    const float* query = (const float*)d_in[0];
    const float* key   = (const float*)d_in[1];
    const float* value = (const float*)d_in[2];
    const float* Wq    = (const float*)d_in[3];
    const float* bq    = (const float*)d_in[4];
    const float* Wk    = (const float*)d_in[5];
    const float* bk    = (const float*)d_in[6];
    const float* Wv    = (const float*)d_in[7];
    const float* bv    = (const float*)d_in[8];
    const float* Wo    = (const float*)d_in[9];
    const float* bo    = (const float*)d_in[10];

    float* out  = (float*)d_out;
    float* attn = out + (size_t)BB * SS * DD;

    cudaFuncSetAttribute(qkv_proj_kernel, cudaFuncAttributeMaxDynamicSharedMemorySize, SMEM_GEMM);
    cudaFuncSetAttribute(out_proj_kernel, cudaFuncAttributeMaxDynamicSharedMemorySize, SMEM_GEMM);
    cudaFuncSetAttribute(attn_kernel,     cudaFuncAttributeMaxDynamicSharedMemorySize, SMEM_ATTN);

    // Q/K/V projections (tensor-core TF32)
    qkv_proj_kernel<<<dim3(8, 32, 3), 256, SMEM_GEMM>>>(query, key, value,
                                                        Wq, Wk, Wv, bq, bk, bv);

    // banded attention (also writes the full attn matrix incl. zeros)
    attn_kernel<<<dim3(SS / 64, BB * HH), 256, SMEM_ATTN>>>(attn);

    // output projection
    out_proj_kernel<<<dim3(8, 32), 256, SMEM_GEMM>>>(Wo, bo, out);
}